// round 10
// baseline (speedup 1.0000x reference)
#include <cuda_runtime.h>
#include <cuda_bf16.h>
#include <cstdint>
#include <math.h>

#define NS 65536
typedef uint32_t u32;
typedef uint64_t u64;

// ===== arch-specific feature gate (tcgen05 only exists on sm_103a pass) ====
#if defined(__CUDA_ARCH__) && (defined(__CUDA_ARCH_FEAT_SM103_ALL) || \
    (defined(__CUDA_ARCH_SPECIFIC__) && (__CUDA_ARCH_SPECIFIC__ == 1030)) || \
    (defined(__CUDA_ARCH_FAMILY_SPECIFIC__) && (__CUDA_ARCH_FAMILY_SPECIFIC__ == 1030)))
#define HAS_TC 1
#else
#define HAS_TC 0
#endif

// ======================= global scratch (no runtime alloc) =================
__device__ __align__(256) unsigned char g_wscr[6u * 256u * 1024u];
__device__ float g_b0p[512], g_wih0p[512], g_b1p[512];
__device__ float g_c0[128u * NS];
__device__ float g_c1[128u * NS];
__device__ float g_hs[128u * NS];
__device__ int   g_use_tc;

__host__ __device__ __forceinline__ u32 swz(u32 b) { return b ^ ((b >> 3) & 0x70); }

// ======================= smem map (bytes) ==================================
#define OFF_TMEM   0
#define OFF_MB     8
#define OFF_B0P    64
#define OFF_WIH    2112
#define OFF_B1P    4160
#define OFF_BD     6208
#define OFF_WO     9280
#define OFF_BO     13376
#define OFF_BBUF   16384
#define OFF_AREG   81920
#define SMEM_BYTES 212992
#define A_H1HI (OFF_AREG)
#define A_H0HI (OFF_AREG + 32768)
#define A_H1LO (OFF_AREG + 65536)
#define A_H0LO (OFF_AREG + 98304)

#define IDESC 0x8400490u
static __device__ __forceinline__ u64 mkdesc(u32 smem_addr) {
    return (u64(2) << 61) | (u64(1) << 46) | (u64(64) << 32) | (u64(1) << 16)
         | ((u64)(smem_addr >> 4) & 0x3FFF);
}

// ======================= PTX helpers =======================================
__device__ __forceinline__ u32 smem_u32(const void* p) {
    u32 a; asm("{ .reg .u64 t; cvta.to.shared.u64 t, %1; cvt.u32.u64 %0, t; }" : "=r"(a) : "l"(p));
    return a;
}
#define MBAR_INIT(a, c) asm volatile("mbarrier.init.shared.b64 [%0], %1;" :: "r"(a), "r"(c) : "memory")
#define MBAR_EXPECT(a, b) asm volatile("mbarrier.arrive.expect_tx.shared.b64 _, [%0], %1;" :: "r"(a), "r"(b) : "memory")
#define MBAR_WAIT(a, ph) do { \
    asm volatile("{\n\t.reg .pred P;\n\tWL%=:\n\t" \
        "mbarrier.try_wait.parity.acquire.cta.shared::cta.b64 P, [%0], %1, 0x989680;\n\t" \
        "@P bra.uni WD%=;\n\tbra.uni WL%=;\n\tWD%=:\n\t}" \
        :: "r"(a), "r"(ph) : "memory"); } while (0)
#define BULKCP(dst, src, mbar) asm volatile( \
    "cp.async.bulk.shared::cluster.global.mbarrier::complete_tx::bytes [%0], [%1], %2, [%3];" \
    :: "r"(dst), "l"(src), "r"(32768u), "r"(mbar) : "memory")
#define FENCE_ASYNC() asm volatile("fence.proxy.async.shared::cta;" ::: "memory")

#if HAS_TC
#define T5_COMMIT(a) asm volatile( \
    "tcgen05.commit.cta_group::1.mbarrier::arrive::one.shared::cluster.b64 [%0];" :: "r"(a) : "memory")
#define T5_ALLOC(a, n) asm volatile( \
    "tcgen05.alloc.cta_group::1.sync.aligned.shared::cta.b32 [%0], %1;" :: "r"(a), "r"(n) : "memory")
#define T5_DEALLOC(t, n) asm volatile( \
    "tcgen05.dealloc.cta_group::1.sync.aligned.b32 %0, %1;" :: "r"(t), "r"(n))
#define T5_WAIT_LD() asm volatile("tcgen05.wait::ld.sync.aligned;" ::: "memory")
#define T5_FENCE_B() asm volatile("tcgen05.fence::before_thread_sync;" ::: "memory")
#define T5_FENCE_A() asm volatile("tcgen05.fence::after_thread_sync;" ::: "memory")
__device__ __forceinline__ void mma_ss(u32 d, u64 ad, u64 bd_, u32 en) {
    asm volatile(
        "{\n\t.reg .pred p;\n\tsetp.ne.u32 p, %4, 0;\n\t"
        "tcgen05.mma.cta_group::1.kind::f16 [%0], %1, %2, %3, {%5,%5,%5,%5}, p;\n\t}"
        :: "r"(d), "l"(ad), "l"(bd_), "r"(IDESC), "r"(en), "r"(0u) : "memory");
}
#define LDTM32(r, a) asm volatile( \
    "tcgen05.ld.sync.aligned.32x32b.x32.b32 " \
    "{%0,%1,%2,%3,%4,%5,%6,%7,%8,%9,%10,%11,%12,%13,%14,%15," \
    "%16,%17,%18,%19,%20,%21,%22,%23,%24,%25,%26,%27,%28,%29,%30,%31}, [%32];" \
    : "=r"((r)[0]), "=r"((r)[1]), "=r"((r)[2]), "=r"((r)[3]), "=r"((r)[4]), "=r"((r)[5]), \
      "=r"((r)[6]), "=r"((r)[7]), "=r"((r)[8]), "=r"((r)[9]), "=r"((r)[10]), "=r"((r)[11]), \
      "=r"((r)[12]), "=r"((r)[13]), "=r"((r)[14]), "=r"((r)[15]), "=r"((r)[16]), "=r"((r)[17]), \
      "=r"((r)[18]), "=r"((r)[19]), "=r"((r)[20]), "=r"((r)[21]), "=r"((r)[22]), "=r"((r)[23]), \
      "=r"((r)[24]), "=r"((r)[25]), "=r"((r)[26]), "=r"((r)[27]), "=r"((r)[28]), "=r"((r)[29]), \
      "=r"((r)[30]), "=r"((r)[31]) : "r"(a))
#else
#define T5_COMMIT(a)      ((void)0)
#define T5_ALLOC(a, n)    ((void)0)
#define T5_DEALLOC(t, n)  ((void)0)
#define T5_WAIT_LD()      ((void)0)
#define T5_FENCE_B()      ((void)0)
#define T5_FENCE_A()      ((void)0)
__device__ __forceinline__ void mma_ss(u32, u64, u64, u32) {}
#define LDTM32(r, a) do { _Pragma("unroll") for (int _i = 0; _i < 32; ++_i) (r)[_i] = 0u; } while (0)
#endif

// ---------------- activations ----------------
__device__ __forceinline__ float sigf(float x) {
    float e = __expf(-x); return __fdividef(1.f, 1.f + e);
}
__device__ __forceinline__ float tanhf_fast(float x) {
    float ax = fabsf(x);
    float e = __expf(-2.f * ax);
    float t = __fdividef(1.f - e, 1.f + e);
    return copysignf(t, x);
}

// ======================= probe =============================================
__global__ void probe() { g_use_tc = HAS_TC; }

// ======================= prep kernel =======================================
__global__ void prep(const float* __restrict__ Whh0, const float* __restrict__ Wih1,
                     const float* __restrict__ Whh1, const float* __restrict__ Wd0,
                     const float* __restrict__ Wd1,  const float* __restrict__ Wd2,
                     const float* __restrict__ Wih0, const float* __restrict__ b0,
                     const float* __restrict__ b1)
{
    int m = blockIdx.x;
    const float* Ws[6] = {Whh0, Wih1, Whh1, Wd0, Wd1, Wd2};
    const float* W = Ws[m];
    unsigned char* dst = g_wscr + (size_t)m * 256u * 1024u;
    bool lstm = (m < 3);
    for (int idx = threadIdx.x; idx < 65536; idx += blockDim.x) {
        float v = W[idx];
        __nv_bfloat16 hi = __float2bfloat16(v);
        __nv_bfloat16 lo = __float2bfloat16(v - __bfloat162float(hi));
        u32 slabpair, byte;
        if (lstm) {
            int gc = idx >> 7, k = idx & 127;
            int g = gc >> 7, u = gc & 127;
            int np = 4 * u + g;
            int nh = np >> 8, r = np & 255;
            int kc = k >> 6, kk = k & 63;
            slabpair = (u32)(kc * 4 + nh * 2);
            byte = (u32)(r * 128 + kk * 2);
        } else {
            int n = idx >> 8, k = idx & 255;
            int kc = k >> 6, kk = k & 63;
            slabpair = (u32)(kc * 2);
            byte = (u32)(n * 128 + kk * 2);
        }
        u32 sw = swz(byte);
        *(__nv_bfloat16*)(dst + (size_t)slabpair * 32768u + sw) = hi;
        *(__nv_bfloat16*)(dst + (size_t)(slabpair + 1) * 32768u + sw) = lo;
    }
    if (m == 0) {
        for (int i = threadIdx.x; i < 512; i += blockDim.x) {
            int g = i >> 7, u = i & 127, np = 4 * u + g;
            g_b0p[np] = b0[i];
            g_wih0p[np] = Wih0[i];
            g_b1p[np] = b1[i];
        }
    }
}

// ======================= orchestrator pipeline =============================
struct PS {
    u32 fullb[2], emptyb[2], bbuf[2], tmem;
    int fph[2], eph[2], used[2], seq;
};
__device__ __forceinline__ void stage(PS& ps, const unsigned char* bsrc, int j) {
    int s = ps.seq & 1;
    if (ps.used[s]) { MBAR_WAIT(ps.emptyb[s], (u32)ps.eph[s]); ps.eph[s] ^= 1; }
    MBAR_EXPECT(ps.fullb[s], 32768u);
    BULKCP(ps.bbuf[s], (u64)(uintptr_t)(bsrc + (size_t)j * 32768u), ps.fullb[s]);
    ps.seq++;
}
__device__ void run_gemm(PS& ps, const unsigned char* bsrc, int nkc, int nnh,
                         u64 ahi, u64 alo, bool first[2])
{
    int nslab = nkc * nnh * 2;
    int seq0 = ps.seq;
    stage(ps, bsrc, 0);
    for (int j = 0; j < nslab; ++j) {
        if (j + 1 < nslab) stage(ps, bsrc, j + 1);
        int s = (seq0 + j) & 1;
        MBAR_WAIT(ps.fullb[s], (u32)ps.fph[s]); ps.fph[s] ^= 1;
        int term = j & 1;
        int nh = (j >> 1) % nnh;
        int kc = j / (2 * nnh);
        u32 d = ps.tmem + (u32)(nh * 256);
        u64 bdesc = mkdesc(ps.bbuf[s]);
        #pragma unroll
        for (int ks = 0; ks < 4; ++ks) {
            u64 bo = bdesc + ks * 2;
            u32 en = first[nh] ? 0u : 1u;
            first[nh] = false;
            mma_ss(d, ahi + (u64)(kc * 1024 + ks * 2), bo, en);
            if (term == 0)
                mma_ss(d, alo + (u64)(kc * 1024 + ks * 2), bo, 1u);
        }
        T5_COMMIT(ps.emptyb[s]); ps.used[s] = 1;
    }
}

// ======================= tcgen05 fused kernel ==============================
__global__ void __launch_bounds__(256, 1) fused_net(
    const float* __restrict__ x, const float* __restrict__ y,
    const float* __restrict__ bd0, const float* __restrict__ bd1,
    const float* __restrict__ bd2, const float* __restrict__ Wo,
    const float* __restrict__ bo, float* __restrict__ out)
{
#if HAS_TC
    extern __shared__ __align__(1024) unsigned char smem[];
    const u32 sb = smem_u32(smem);
    const int tid = threadIdx.x;
    const int wrp = tid >> 5, lane = tid & 31;
    const int sp = wrp & 3, cho = wrp >> 2;
    const int row_l = sp * 32 + lane;
    const int row0 = blockIdx.x * 128;
    const int grow = row0 + row_l;
    float* smf = (float*)smem;

    if (tid == 0) {
        for (int i = 0; i < 5; ++i) MBAR_INIT(sb + OFF_MB + 8 * i, 1);
    }
    if (wrp == 0) T5_ALLOC(sb + OFF_TMEM, 512);
    for (int i = tid; i < 512; i += 256) {
        smf[(OFF_B0P >> 2) + i] = g_b0p[i];
        smf[(OFF_WIH >> 2) + i] = g_wih0p[i];
        smf[(OFF_B1P >> 2) + i] = g_b1p[i];
    }
    if (tid < 256) {
        smf[(OFF_BD >> 2) + tid] = bd0[tid];
        smf[(OFF_BD >> 2) + 256 + tid] = bd1[tid];
        smf[(OFF_BD >> 2) + 512 + tid] = bd2[tid];
    }
    for (int i = tid; i < 1024; i += 256) smf[(OFF_WO >> 2) + i] = Wo[i];
    if (tid < 4) smf[(OFF_BO >> 2) + tid] = bo[tid];
    __syncthreads();
    u32 tmem; asm volatile("ld.shared.b32 %0, [%1];" : "=r"(tmem) : "r"(sb + OFF_TMEM));

    PS ps;
    ps.fullb[0] = sb + OFF_MB;       ps.fullb[1] = sb + OFF_MB + 8;
    ps.emptyb[0] = sb + OFF_MB + 16; ps.emptyb[1] = sb + OFF_MB + 24;
    const u32 gdone = sb + OFF_MB + 32;
    ps.bbuf[0] = sb + OFF_BBUF; ps.bbuf[1] = sb + OFF_BBUF + 32768;
    ps.fph[0] = ps.fph[1] = ps.eph[0] = ps.eph[1] = 0;
    ps.used[0] = ps.used[1] = 0; ps.seq = 0;
    ps.tmem = tmem;
    int gph = 0;

    const float xv = x[grow], yv = y[grow];
    const float xn = 2.f * xv - 1.f, yn = 2.f * yv - 1.f;

    const u64 dH0hi = mkdesc(sb + A_H0HI), dH0lo = mkdesc(sb + A_H0LO);
    const u64 dH1hi = mkdesc(sb + A_H1HI), dH1lo = mkdesc(sb + A_H1LO);

    const int u_base = cho * 64;
    const u32 tm_lane = tmem + ((u32)sp << 21);

    for (int t = 0; t < 6; ++t) {
        // ---------- layer 0 GEMM ----------
        if (t > 0) {
            if (tid == 0) {
                bool f2[2] = {true, true};
                run_gemm(ps, g_wscr, 2, 2, dH0hi, dH0lo, f2);
                T5_COMMIT(gdone);
            }
            MBAR_WAIT(gdone, (u32)gph); gph ^= 1;
            T5_FENCE_A();
        }
        // ---------- layer 0 epilogue ----------
        {
            float ft;
            if      (t == 0) ft = xn;
            else if (t == 1) ft = yn;
            else if (t == 2) ft = xn + yn;
            else if (t == 3) ft = xn - yn;
            else if (t == 4) ft = xn * yn;
            else             ft = xn * xn + yn * yn;
            #pragma unroll
            for (int ch = 0; ch < 8; ++ch) {
                const int cb = 256 * cho + 32 * ch;
                const int u0 = u_base + 8 * ch;
                u32 r[32];
                if (t > 0) { LDTM32(r, tm_lane + (u32)cb); T5_WAIT_LD(); }
                #pragma unroll
                for (int j = 0; j < 8; j += 2) {
                    float h2[2];
                    #pragma unroll
                    for (int q = 0; q < 2; ++q) {
                        int u = u0 + j + q, col = cb + 4 * (j + q);
                        float gi = smf[(OFF_B0P >> 2) + col]     + ft * smf[(OFF_WIH >> 2) + col];
                        float gf = smf[(OFF_B0P >> 2) + col + 1] + ft * smf[(OFF_WIH >> 2) + col + 1];
                        float gg = smf[(OFF_B0P >> 2) + col + 2] + ft * smf[(OFF_WIH >> 2) + col + 2];
                        float go = smf[(OFF_B0P >> 2) + col + 3] + ft * smf[(OFF_WIH >> 2) + col + 3];
                        if (t > 0) {
                            gi += __uint_as_float(r[4 * (j + q)]);
                            gf += __uint_as_float(r[4 * (j + q) + 1]);
                            gg += __uint_as_float(r[4 * (j + q) + 2]);
                            go += __uint_as_float(r[4 * (j + q) + 3]);
                        }
                        float co = (t > 0) ? g_c0[(size_t)u * NS + grow] : 0.f;
                        float cn = sigf(gf) * co + sigf(gi) * tanhf_fast(gg);
                        float hn = sigf(go) * tanhf_fast(cn);
                        g_c0[(size_t)u * NS + grow] = cn;
                        h2[q] = hn;
                    }
                    int u = u0 + j;
                    u32 byte = swz((u32)(row_l * 128 + (u & 63) * 2));
                    u32 base = (u32)((u >> 6) * 16384) + byte;
                    __nv_bfloat16 h0b = __float2bfloat16(h2[0]);
                    __nv_bfloat16 h1b = __float2bfloat16(h2[1]);
                    __nv_bfloat162 hp; hp.x = h0b; hp.y = h1b;
                    __nv_bfloat162 lp;
                    lp.x = __float2bfloat16(h2[0] - __bfloat162float(h0b));
                    lp.y = __float2bfloat16(h2[1] - __bfloat162float(h1b));
                    *(__nv_bfloat162*)(smem + A_H0HI + base) = hp;
                    *(__nv_bfloat162*)(smem + A_H0LO + base) = lp;
                }
            }
            T5_FENCE_B();
            FENCE_ASYNC();
            __syncthreads();
        }
        // ---------- layer 1 GEMM ----------
        {
            if (tid == 0) {
                bool f2[2] = {true, true};
                run_gemm(ps, g_wscr + 256u * 1024u, 2, 2, dH0hi, dH0lo, f2);
                if (t > 0)
                    run_gemm(ps, g_wscr + 512u * 1024u, 2, 2, dH1hi, dH1lo, f2);
                T5_COMMIT(gdone);
            }
            MBAR_WAIT(gdone, (u32)gph); gph ^= 1;
            T5_FENCE_A();
        }
        // ---------- layer 1 epilogue ----------
        {
            #pragma unroll
            for (int ch = 0; ch < 8; ++ch) {
                const int cb = 256 * cho + 32 * ch;
                const int u0 = u_base + 8 * ch;
                u32 r[32];
                LDTM32(r, tm_lane + (u32)cb); T5_WAIT_LD();
                #pragma unroll
                for (int j = 0; j < 8; j += 2) {
                    float h2[2], m2[2];
                    #pragma unroll
                    for (int q = 0; q < 2; ++q) {
                        int u = u0 + j + q, col = cb + 4 * (j + q);
                        float gi = __uint_as_float(r[4 * (j + q)])     + smf[(OFF_B1P >> 2) + col];
                        float gf = __uint_as_float(r[4 * (j + q) + 1]) + smf[(OFF_B1P >> 2) + col + 1];
                        float gg = __uint_as_float(r[4 * (j + q) + 2]) + smf[(OFF_B1P >> 2) + col + 2];
                        float go = __uint_as_float(r[4 * (j + q) + 3]) + smf[(OFF_B1P >> 2) + col + 3];
                        float co = (t > 0) ? g_c1[(size_t)u * NS + grow] : 0.f;
                        float cn = sigf(gf) * co + sigf(gi) * tanhf_fast(gg);
                        float hn = sigf(go) * tanhf_fast(cn);
                        g_c1[(size_t)u * NS + grow] = cn;
                        float s = (t == 0) ? hn : (g_hs[(size_t)u * NS + grow] + hn);
                        if (t < 5) g_hs[(size_t)u * NS + grow] = s;
                        h2[q] = hn;
                        m2[q] = s * (1.f / 6.f);
                    }
                    int u = u0 + j;
                    u32 byte = swz((u32)(row_l * 128 + (u & 63) * 2));
                    u32 base = (u32)((u >> 6) * 16384) + byte;
                    __nv_bfloat16 h0b = __float2bfloat16(h2[0]);
                    __nv_bfloat16 h1b = __float2bfloat16(h2[1]);
                    __nv_bfloat162 hp; hp.x = h0b; hp.y = h1b;
                    __nv_bfloat162 lp;
                    lp.x = __float2bfloat16(h2[0] - __bfloat162float(h0b));
                    lp.y = __float2bfloat16(h2[1] - __bfloat162float(h1b));
                    *(__nv_bfloat162*)(smem + A_H1HI + base) = hp;
                    *(__nv_bfloat162*)(smem + A_H1LO + base) = lp;
                    if (t == 5) {
                        __nv_bfloat16 m0b = __float2bfloat16(m2[0]);
                        __nv_bfloat16 m1b = __float2bfloat16(m2[1]);
                        __nv_bfloat162 mp; mp.x = m0b; mp.y = m1b;
                        __nv_bfloat162 mlp;
                        mlp.x = __float2bfloat16(m2[0] - __bfloat162float(m0b));
                        mlp.y = __float2bfloat16(m2[1] - __bfloat162float(m1b));
                        *(__nv_bfloat162*)(smem + A_H0HI + base) = mp;
                        *(__nv_bfloat162*)(smem + A_H0LO + base) = mlp;
                    }
                }
            }
            T5_FENCE_B();
            FENCE_ASYNC();
            __syncthreads();
        }
    }

    // ---------- dense stack ----------
    const u64 dAhi = mkdesc(sb + OFF_AREG);
    const u64 dAlo = mkdesc(sb + OFF_AREG + 65536);
    for (int l = 0; l < 3; ++l) {
        if (tid == 0) {
            bool f2[2] = {true, true};
            run_gemm(ps, g_wscr + (size_t)(3 + l) * 256u * 1024u, 4, 1, dAhi, dAlo, f2);
            T5_COMMIT(gdone);
        }
        MBAR_WAIT(gdone, (u32)gph); gph ^= 1;
        T5_FENCE_A();
        #pragma unroll
        for (int ch = 0; ch < 4; ++ch) {
            const int cb = 128 * cho + 32 * ch;
            u32 r[32];
            LDTM32(r, tm_lane + (u32)cb); T5_WAIT_LD();
            #pragma unroll
            for (int j = 0; j < 32; j += 2) {
                int n = cb + j;
                float a0 = tanhf_fast(__uint_as_float(r[j])     + smf[(OFF_BD >> 2) + l * 256 + n]);
                float a1 = tanhf_fast(__uint_as_float(r[j + 1]) + smf[(OFF_BD >> 2) + l * 256 + n + 1]);
                u32 byte = swz((u32)(row_l * 128 + (n & 63) * 2));
                u32 base = (u32)((n >> 6) * 16384) + byte;
                __nv_bfloat16 b0b = __float2bfloat16(a0);
                __nv_bfloat16 b1b = __float2bfloat16(a1);
                __nv_bfloat162 hp; hp.x = b0b; hp.y = b1b;
                __nv_bfloat162 lp;
                lp.x = __float2bfloat16(a0 - __bfloat162float(b0b));
                lp.y = __float2bfloat16(a1 - __bfloat162float(b1b));
                *(__nv_bfloat162*)(smem + OFF_AREG + base) = hp;
                *(__nv_bfloat162*)(smem + OFF_AREG + 65536 + base) = lp;
            }
        }
        T5_FENCE_B();
        FENCE_ASYNC();
        __syncthreads();
    }

    // ---------- output head ----------
    {
        int rh = tid >> 1;
        int ob = (tid & 1) * 2;
        float s0 = 0.f, s1 = 0.f;
        const float* wo = smf + (OFF_WO >> 2);
        #pragma unroll 8
        for (int k = 0; k < 256; k += 2) {
            u32 byte = swz((u32)(rh * 128 + (k & 63) * 2));
            u32 base = (u32)((k >> 6) * 16384) + byte;
            __nv_bfloat162 hp = *(__nv_bfloat162*)(smem + OFF_AREG + base);
            __nv_bfloat162 lp = *(__nv_bfloat162*)(smem + OFF_AREG + 65536 + base);
            float a0 = __bfloat162float(hp.x) + __bfloat162float(lp.x);
            float a1 = __bfloat162float(hp.y) + __bfloat162float(lp.y);
            s0 += a0 * wo[ob * 256 + k] + a1 * wo[ob * 256 + k + 1];
            s1 += a0 * wo[(ob + 1) * 256 + k] + a1 * wo[(ob + 1) * 256 + k + 1];
        }
        out[(size_t)(row0 + rh) * 4 + ob]     = s0 + smf[(OFF_BO >> 2) + ob];
        out[(size_t)(row0 + rh) * 4 + ob + 1] = s1 + smf[(OFF_BO >> 2) + ob + 1];
    }

    __syncthreads();
    if (wrp == 0) T5_DEALLOC(tmem, 512);
#endif  // HAS_TC
}

// ===========================================================================
// ================== FFMA2 fallback (verified round-6 kernel) ===============
// ===========================================================================
#define ASTR 260
#define BSTR 514

__device__ __forceinline__ u64 pk2(float a, float b) {
    u64 r; asm("mov.b64 %0,{%1,%2};" : "=l"(r) : "f"(a), "f"(b)); return r;
}
__device__ __forceinline__ void upk2(u64 v, float& a, float& b) {
    asm("mov.b64 {%0,%1},%2;" : "=f"(a), "=f"(b) : "l"(v));
}
__device__ __forceinline__ void ffma2(u64& d, u64 a, u64 b) {
    asm("fma.rn.f32x2 %0,%1,%2,%0;" : "+l"(d) : "l"(a), "l"(b));
}

template<int K, int NCOL>
__device__ __forceinline__ void fb_gemm(const float* __restrict__ W,
                                        const float* __restrict__ Abase,
                                        u64 (&acc)[8][4],
                                        float* Bs, int tid, int tx, int ty)
{
    constexpr int P = NCOL / 128;
    const float* Arow = Abase + ty * 8 * ASTR;
    for (int k0 = 0; k0 < K; k0 += 16) {
        __syncthreads();
        const float4* W4 = (const float4*)W;
        #pragma unroll
        for (int it = 0; it < NCOL / 64; ++it) {
            int v = tid + it * 256;
            int col = v >> 2, q = v & 3;
            float4 f = W4[col * (K / 4) + (k0 >> 2) + q];
            float* bp = Bs + (q * 4) * BSTR + col;
            bp[0] = f.x; bp[BSTR] = f.y; bp[2 * BSTR] = f.z; bp[3 * BSTR] = f.w;
        }
        __syncthreads();
        #pragma unroll
        for (int kq = 0; kq < 4; ++kq) {
            float4 a4[8];
            #pragma unroll
            for (int i = 0; i < 8; ++i)
                a4[i] = *(const float4*)(Arow + i * ASTR + k0 + kq * 4);
            #pragma unroll
            for (int kk = 0; kk < 4; ++kk) {
                const u64* brow = (const u64*)(Bs + (kq * 4 + kk) * BSTR);
                u64 b[4];
                #pragma unroll
                for (int p = 0; p < P; ++p) b[p] = brow[tx + 64 * p];
                #pragma unroll
                for (int i = 0; i < 8; ++i) {
                    float av = (kk == 0) ? a4[i].x : (kk == 1) ? a4[i].y
                             : (kk == 2) ? a4[i].z : a4[i].w;
                    u64 a2 = pk2(av, av);
                    #pragma unroll
                    for (int p = 0; p < P; ++p) ffma2(acc[i][p], a2, b[p]);
                }
            }
        }
    }
}

__global__ void __launch_bounds__(256, 2) fused_ffma(
    const float* __restrict__ x, const float* __restrict__ y,
    const float* __restrict__ Wih0, const float* __restrict__ Whh0, const float* __restrict__ b0,
    const float* __restrict__ Wih1, const float* __restrict__ Whh1, const float* __restrict__ b1,
    const float* __restrict__ Wd0, const float* __restrict__ bd0,
    const float* __restrict__ Wd1, const float* __restrict__ bd1,
    const float* __restrict__ Wd2, const float* __restrict__ bd2,
    const float* __restrict__ Wo,  const float* __restrict__ bo,
    float* __restrict__ out)
{
    if (g_use_tc) return;
    extern __shared__ float smemf[];
    float* Bs = smemf;
    float* R2 = smemf + 16 * BSTR;
    float* A0 = R2 + 32 * ASTR;

    const int tid = threadIdx.x, tx = tid & 63, ty = tid >> 6;
    const int row0 = blockIdx.x * 32;
    const int u0 = 2 * tx;

    float xn[8], yn[8];
    #pragma unroll
    for (int i = 0; i < 8; ++i) {
        int r = row0 + ty * 8 + i;
        xn[i] = 2.f * x[r] - 1.f;
        yn[i] = 2.f * y[r] - 1.f;
    }

    float c1r[16];
    #pragma unroll
    for (int i = 0; i < 16; ++i) c1r[i] = 0.f;

    u64 acc[8][4];

    for (int t = 0; t < 6; ++t) {
        {
            u64 bv[4], wv[4];
            #pragma unroll
            for (int p = 0; p < 4; ++p) {
                bv[p] = *(const u64*)(b0 + u0 + 128 * p);
                wv[p] = *(const u64*)(Wih0 + u0 + 128 * p);
            }
            #pragma unroll
            for (int i = 0; i < 8; ++i) {
                float f;
                if      (t == 0) f = xn[i];
                else if (t == 1) f = yn[i];
                else if (t == 2) f = xn[i] + yn[i];
                else if (t == 3) f = xn[i] - yn[i];
                else if (t == 4) f = xn[i] * yn[i];
                else             f = xn[i] * xn[i] + yn[i] * yn[i];
                u64 f2 = pk2(f, f);
                #pragma unroll
                for (int p = 0; p < 4; ++p) { acc[i][p] = bv[p]; ffma2(acc[i][p], f2, wv[p]); }
            }
            if (t > 0) fb_gemm<128, 512>(Whh0, R2, acc, Bs, tid, tx, ty);
            __syncthreads();
            #pragma unroll
            for (int i = 0; i < 8; ++i) {
                float* row = R2 + (ty * 8 + i) * ASTR;
                float gi0, gi1, gf0, gf1, gg0, gg1, go0, go1;
                upk2(acc[i][0], gi0, gi1);
                upk2(acc[i][1], gf0, gf1);
                upk2(acc[i][2], gg0, gg1);
                upk2(acc[i][3], go0, go1);
                float co0 = 0.f, co1 = 0.f;
                if (t > 0) { float2 cc = *(float2*)(row + 128 + u0); co0 = cc.x; co1 = cc.y; }
                float cn0 = sigf(gf0) * co0 + sigf(gi0) * tanhf_fast(gg0);
                float cn1 = sigf(gf1) * co1 + sigf(gi1) * tanhf_fast(gg1);
                float hn0 = sigf(go0) * tanhf_fast(cn0);
                float hn1 = sigf(go1) * tanhf_fast(cn1);
                *(float2*)(row + 128 + u0) = make_float2(cn0, cn1);
                *(float2*)(row + u0)       = make_float2(hn0, hn1);
            }
        }
        {
            #pragma unroll
            for (int i = 0; i < 8; ++i)
                #pragma unroll
                for (int p = 0; p < 4; ++p) acc[i][p] = *(const u64*)(b1 + u0 + 128 * p);
            fb_gemm<128, 512>(Wih1, R2, acc, Bs, tid, tx, ty);
            if (t > 0) fb_gemm<128, 512>(Whh1, A0, acc, Bs, tid, tx, ty);
            __syncthreads();
            #pragma unroll
            for (int i = 0; i < 8; ++i) {
                float* row = A0 + (ty * 8 + i) * ASTR;
                float gi0, gi1, gf0, gf1, gg0, gg1, go0, go1;
                upk2(acc[i][0], gi0, gi1);
                upk2(acc[i][1], gf0, gf1);
                upk2(acc[i][2], gg0, gg1);
                upk2(acc[i][3], go0, go1);
                float co0 = c1r[i * 2], co1 = c1r[i * 2 + 1];
                float cn0 = sigf(gf0) * co0 + sigf(gi0) * tanhf_fast(gg0);
                float cn1 = sigf(gf1) * co1 + sigf(gi1) * tanhf_fast(gg1);
                float hn0 = sigf(go0) * tanhf_fast(cn0);
                float hn1 = sigf(go1) * tanhf_fast(cn1);
                c1r[i * 2]     = cn0;
                c1r[i * 2 + 1] = cn1;
                *(float2*)(row + u0) = make_float2(hn0, hn1);
                float s0, s1;
                if (t == 0) { s0 = hn0; s1 = hn1; }
                else { float2 sv = *(float2*)(row + 128 + u0); s0 = sv.x + hn0; s1 = sv.y + hn1; }
                if (t == 5) { s0 *= (1.f / 6.f); s1 *= (1.f / 6.f); }
                *(float2*)(row + 128 + u0) = make_float2(s0, s1);
            }
        }
    }

    const float* Wds[3] = {Wd0, Wd1, Wd2};
    const float* bds[3] = {bd0, bd1, bd2};
    float* ping = A0;
    float* pong = R2;
    for (int l = 0; l < 3; ++l) {
        #pragma unroll
        for (int i = 0; i < 8; ++i)
            #pragma unroll
            for (int p = 0; p < 2; ++p) acc[i][p] = *(const u64*)(bds[l] + u0 + 128 * p);
        fb_gemm<256, 256>(Wds[l], ping, acc, Bs, tid, tx, ty);
        __syncthreads();
        #pragma unroll
        for (int i = 0; i < 8; ++i) {
            float* row = pong + (ty * 8 + i) * ASTR;
            #pragma unroll
            for (int p = 0; p < 2; ++p) {
                float a0v, a1v; upk2(acc[i][p], a0v, a1v);
                *(float2*)(row + u0 + 128 * p) =
                    make_float2(tanhf_fast(a0v), tanhf_fast(a1v));
            }
        }
        float* tmp = ping; ping = pong; pong = tmp;
    }
    __syncthreads();

    if (tid < 128) {
        int r = tid >> 2, o = tid & 3;
        const float* a = ping + r * ASTR;
        const float* w = Wo + o * 256;
        float s0 = 0.f, s1 = 0.f, s2 = 0.f, s3 = 0.f;
        #pragma unroll 4
        for (int k = 0; k < 256; k += 4) {
            s0 += a[k]     * w[k];
            s1 += a[k + 1] * w[k + 1];
            s2 += a[k + 2] * w[k + 2];
            s3 += a[k + 3] * w[k + 3];
        }
        out[(row0 + r) * 4 + o] = bo[o] + ((s0 + s1) + (s2 + s3));
    }
}

// ======================= host launcher =====================================
extern "C" void kernel_launch(void* const* d_in, const int* in_sizes, int n_in,
                              void* d_out, int out_size)
{
    const float* x    = (const float*)d_in[0];
    const float* y    = (const float*)d_in[1];
    const float* Wih0 = (const float*)d_in[2];
    const float* Whh0 = (const float*)d_in[3];
    const float* b0   = (const float*)d_in[4];
    const float* Wih1 = (const float*)d_in[5];
    const float* Whh1 = (const float*)d_in[6];
    const float* b1   = (const float*)d_in[7];
    const float* Wd0  = (const float*)d_in[8];
    const float* bd0  = (const float*)d_in[9];
    const float* Wd1  = (const float*)d_in[10];
    const float* bd1  = (const float*)d_in[11];
    const float* Wd2  = (const float*)d_in[12];
    const float* bd2  = (const float*)d_in[13];
    const float* Wo   = (const float*)d_in[14];
    const float* bo   = (const float*)d_in[15];
    float* out = (float*)d_out;

    probe<<<1, 1>>>();
    prep<<<6, 256>>>(Whh0, Wih1, Whh1, Wd0, Wd1, Wd2, Wih0, b0, b1);

    cudaFuncSetAttribute(fused_net, cudaFuncAttributeMaxDynamicSharedMemorySize, SMEM_BYTES);
    fused_net<<<NS / 128, 256, SMEM_BYTES>>>(x, y, bd0, bd1, bd2, Wo, bo, out);

    const int fb_smem = (16 * BSTR + 2 * 32 * ASTR) * (int)sizeof(float);
    cudaFuncSetAttribute(fused_ffma, cudaFuncAttributeMaxDynamicSharedMemorySize, fb_smem);
    fused_ffma<<<NS / 32, 256, fb_smem>>>(x, y,
                                          Wih0, Whh0, b0, Wih1, Whh1, b1,
                                          Wd0, bd0, Wd1, bd1, Wd2, bd2,
                                          Wo, bo, out);
}

// round 11
// speedup vs baseline: 1.6415x; 1.6415x over previous
#include <cuda_runtime.h>
#include <cuda_bf16.h>
#include <cstdint>
#include <math.h>

#define NS 65536
typedef uint32_t u32;
typedef uint64_t u64;

// ===== arch-specific feature gate (tcgen05 only exists on sm_103a pass) ====
#if defined(__CUDA_ARCH__) && (defined(__CUDA_ARCH_FEAT_SM103_ALL) || \
    (defined(__CUDA_ARCH_SPECIFIC__) && (__CUDA_ARCH_SPECIFIC__ == 1030)) || \
    (defined(__CUDA_ARCH_FAMILY_SPECIFIC__) && (__CUDA_ARCH_FAMILY_SPECIFIC__ == 1030)))
#define HAS_TC 1
#else
#define HAS_TC 0
#endif

// ======================= global scratch (no runtime alloc) =================
__device__ __align__(256) unsigned char g_wscr[6u * 256u * 1024u];
__device__ float g_b0p[512], g_wih0p[512], g_b1p[512];
__device__ float g_c0[128u * NS];
__device__ float g_c1[128u * NS];
__device__ float g_hs[128u * NS];
__device__ int   g_use_tc;

__host__ __device__ __forceinline__ u32 swz(u32 b) { return b ^ ((b >> 3) & 0x70); }

// ======================= smem map (bytes) ==================================
#define OFF_TMEM   0
#define OFF_MB     8          // full0,full1,empty0,empty1,gd0,gd1
#define OFF_B0P    64
#define OFF_WIH    2112
#define OFF_B1P    4160
#define OFF_BD     6208
#define OFF_WO     9280
#define OFF_BO     13376
#define OFF_BBUF   16384      // 2 x 32KB
#define OFF_AREG   81920      // 128KB
#define SMEM_BYTES 212992
#define A_H1HI (OFF_AREG)
#define A_H0HI (OFF_AREG + 32768)
#define A_H1LO (OFF_AREG + 65536)
#define A_H0LO (OFF_AREG + 98304)

#define IDESC 0x8400490u      // f32 accum, bf16xbf16, M=128, N=256
static __device__ __forceinline__ u64 mkdesc(u32 smem_addr) {
    return (u64(2) << 61) | (u64(1) << 46) | (u64(64) << 32) | (u64(1) << 16)
         | ((u64)(smem_addr >> 4) & 0x3FFF);
}

// ======================= PTX helpers =======================================
__device__ __forceinline__ u32 smem_u32(const void* p) {
    u32 a; asm("{ .reg .u64 t; cvta.to.shared.u64 t, %1; cvt.u32.u64 %0, t; }" : "=r"(a) : "l"(p));
    return a;
}
#define MBAR_INIT(a, c) asm volatile("mbarrier.init.shared.b64 [%0], %1;" :: "r"(a), "r"(c) : "memory")
#define MBAR_EXPECT(a, b) asm volatile("mbarrier.arrive.expect_tx.shared.b64 _, [%0], %1;" :: "r"(a), "r"(b) : "memory")
#define MBAR_WAIT(a, ph) do { \
    asm volatile("{\n\t.reg .pred P;\n\tWL%=:\n\t" \
        "mbarrier.try_wait.parity.acquire.cta.shared::cta.b64 P, [%0], %1, 0x989680;\n\t" \
        "@P bra.uni WD%=;\n\tbra.uni WL%=;\n\tWD%=:\n\t}" \
        :: "r"(a), "r"(ph) : "memory"); } while (0)
#define BULKCP(dst, src, mbar) asm volatile( \
    "cp.async.bulk.shared::cluster.global.mbarrier::complete_tx::bytes [%0], [%1], %2, [%3];" \
    :: "r"(dst), "l"(src), "r"(32768u), "r"(mbar) : "memory")
#define FENCE_ASYNC() asm volatile("fence.proxy.async.shared::cta;" ::: "memory")

#if HAS_TC
#define T5_COMMIT(a) asm volatile( \
    "tcgen05.commit.cta_group::1.mbarrier::arrive::one.shared::cluster.b64 [%0];" :: "r"(a) : "memory")
#define T5_ALLOC(a, n) asm volatile( \
    "tcgen05.alloc.cta_group::1.sync.aligned.shared::cta.b32 [%0], %1;" :: "r"(a), "r"(n) : "memory")
#define T5_DEALLOC(t, n) asm volatile( \
    "tcgen05.dealloc.cta_group::1.sync.aligned.b32 %0, %1;" :: "r"(t), "r"(n))
#define T5_WAIT_LD() asm volatile("tcgen05.wait::ld.sync.aligned;" ::: "memory")
#define T5_FENCE_B() asm volatile("tcgen05.fence::before_thread_sync;" ::: "memory")
#define T5_FENCE_A() asm volatile("tcgen05.fence::after_thread_sync;" ::: "memory")
__device__ __forceinline__ void mma_ss(u32 d, u64 ad, u64 bd_, u32 en) {
    asm volatile(
        "{\n\t.reg .pred p;\n\tsetp.ne.u32 p, %4, 0;\n\t"
        "tcgen05.mma.cta_group::1.kind::f16 [%0], %1, %2, %3, {%5,%5,%5,%5}, p;\n\t}"
        :: "r"(d), "l"(ad), "l"(bd_), "r"(IDESC), "r"(en), "r"(0u) : "memory");
}
#define LDTM32(r, a) asm volatile( \
    "tcgen05.ld.sync.aligned.32x32b.x32.b32 " \
    "{%0,%1,%2,%3,%4,%5,%6,%7,%8,%9,%10,%11,%12,%13,%14,%15," \
    "%16,%17,%18,%19,%20,%21,%22,%23,%24,%25,%26,%27,%28,%29,%30,%31}, [%32];" \
    : "=r"((r)[0]), "=r"((r)[1]), "=r"((r)[2]), "=r"((r)[3]), "=r"((r)[4]), "=r"((r)[5]), \
      "=r"((r)[6]), "=r"((r)[7]), "=r"((r)[8]), "=r"((r)[9]), "=r"((r)[10]), "=r"((r)[11]), \
      "=r"((r)[12]), "=r"((r)[13]), "=r"((r)[14]), "=r"((r)[15]), "=r"((r)[16]), "=r"((r)[17]), \
      "=r"((r)[18]), "=r"((r)[19]), "=r"((r)[20]), "=r"((r)[21]), "=r"((r)[22]), "=r"((r)[23]), \
      "=r"((r)[24]), "=r"((r)[25]), "=r"((r)[26]), "=r"((r)[27]), "=r"((r)[28]), "=r"((r)[29]), \
      "=r"((r)[30]), "=r"((r)[31]) : "r"(a))
#else
#define T5_COMMIT(a)      ((void)0)
#define T5_ALLOC(a, n)    ((void)0)
#define T5_DEALLOC(t, n)  ((void)0)
#define T5_WAIT_LD()      ((void)0)
#define T5_FENCE_B()      ((void)0)
#define T5_FENCE_A()      ((void)0)
__device__ __forceinline__ void mma_ss(u32, u64, u64, u32) {}
#define LDTM32(r, a) do { _Pragma("unroll") for (int _i = 0; _i < 32; ++_i) (r)[_i] = 0u; } while (0)
#endif

// ---------------- activations ----------------
__device__ __forceinline__ float sigf(float x) {
    float e = __expf(-x); return __fdividef(1.f, 1.f + e);
}
__device__ __forceinline__ float tanhf_fast(float x) {
    float ax = fabsf(x);
    float e = __expf(-2.f * ax);
    float t = __fdividef(1.f - e, 1.f + e);
    return copysignf(t, x);
}
__device__ __forceinline__ float tanha(float x) {
    float r; asm("tanh.approx.f32 %0, %1;" : "=f"(r) : "f"(x)); return r;
}
__device__ __forceinline__ float siga(float x) {
    return fmaf(tanha(x * 0.5f), 0.5f, 0.5f);
}
__device__ __forceinline__ u32 pack_hl(float a, float b, u32& lo) {
    __nv_bfloat162 hp, lp;
    hp.x = __float2bfloat16(a); hp.y = __float2bfloat16(b);
    lp.x = __float2bfloat16(a - __bfloat162float(hp.x));
    lp.y = __float2bfloat16(b - __bfloat162float(hp.y));
    lo = *(u32*)&lp;
    return *(u32*)&hp;
}

// ======================= probe =============================================
__global__ void probe() { g_use_tc = HAS_TC; }

// ======================= prep kernel =======================================
__global__ void prep(const float* __restrict__ Whh0, const float* __restrict__ Wih1,
                     const float* __restrict__ Whh1, const float* __restrict__ Wd0,
                     const float* __restrict__ Wd1,  const float* __restrict__ Wd2,
                     const float* __restrict__ Wih0, const float* __restrict__ b0,
                     const float* __restrict__ b1)
{
    int m = blockIdx.x;
    const float* Ws[6] = {Whh0, Wih1, Whh1, Wd0, Wd1, Wd2};
    const float* W = Ws[m];
    unsigned char* dst = g_wscr + (size_t)m * 256u * 1024u;
    bool lstm = (m < 3);
    for (int idx = threadIdx.x; idx < 65536; idx += blockDim.x) {
        float v = W[idx];
        __nv_bfloat16 hi = __float2bfloat16(v);
        __nv_bfloat16 lo = __float2bfloat16(v - __bfloat162float(hi));
        u32 slabpair, byte;
        if (lstm) {
            int gc = idx >> 7, k = idx & 127;
            int g = gc >> 7, u = gc & 127;
            int np = 4 * u + g;
            int nh = np >> 8, r = np & 255;
            int kc = k >> 6, kk = k & 63;
            slabpair = (u32)(kc * 4 + nh * 2);
            byte = (u32)(r * 128 + kk * 2);
        } else {
            int n = idx >> 8, k = idx & 255;
            int kc = k >> 6, kk = k & 63;
            slabpair = (u32)(kc * 2);
            byte = (u32)(n * 128 + kk * 2);
        }
        u32 sw = swz(byte);
        *(__nv_bfloat16*)(dst + (size_t)slabpair * 32768u + sw) = hi;
        *(__nv_bfloat16*)(dst + (size_t)(slabpair + 1) * 32768u + sw) = lo;
    }
    if (m == 0) {
        for (int i = threadIdx.x; i < 512; i += blockDim.x) {
            int g = i >> 7, u = i & 127, np = 4 * u + g;
            g_b0p[np] = b0[i];
            g_wih0p[np] = Wih0[i];
            g_b1p[np] = b1[i];
        }
    }
}

// ======================= orchestrator pipeline =============================
struct PS {
    u32 fullb[2], emptyb[2], bbuf[2];
    int fph[2], eph[2], used[2], sseq, iseq;
};
__device__ __forceinline__ void stage_src(PS& ps, u64 src) {
    int s = ps.sseq & 1; ps.sseq++;
    if (ps.used[s]) { MBAR_WAIT(ps.emptyb[s], (u32)ps.eph[s]); ps.eph[s] ^= 1; }
    ps.used[s] = 1;
    MBAR_EXPECT(ps.fullb[s], 32768u);
    BULKCP(ps.bbuf[s], src, ps.fullb[s]);
}
// Slabs alternate hi/lo (hl=j&1). hi: Ahi*B + Alo*B; lo: Ahi*B (bf16x3).
// Alo desc = Ahi + 4096 units (64KB). Commits gd0 after slab c0i, gd1 at end.
__device__ void run_plan(PS& ps, const u64* src, const u64* ad, const u32* dst,
                         int n, int f1i, int c0i, u32 gd0, u32 gd1)
{
    stage_src(ps, src[0]);
    for (int j = 0; j < n; ++j) {
        if (j + 1 < n) stage_src(ps, src[j + 1]);
        int s = ps.iseq & 1; ps.iseq++;
        MBAR_WAIT(ps.fullb[s], (u32)ps.fph[s]); ps.fph[s] ^= 1;
        u64 bd = mkdesc(ps.bbuf[s]);
        int hl = j & 1;
        #pragma unroll
        for (int ks = 0; ks < 4; ++ks) {
            u32 en = (ks == 0 && (j == 0 || j == f1i)) ? 0u : 1u;
            mma_ss(dst[j], ad[j] + (u64)(ks * 2), bd + (u64)(ks * 2), en);
            if (hl == 0)
                mma_ss(dst[j], ad[j] + 4096u + (u64)(ks * 2), bd + (u64)(ks * 2), 1u);
        }
        T5_COMMIT(ps.emptyb[s]);
        if (j == c0i) T5_COMMIT(gd0);
    }
    T5_COMMIT(gd1);
}

// ======================= tcgen05 fused kernel ==============================
__global__ void __launch_bounds__(512, 1) fused_net(
    const float* __restrict__ x, const float* __restrict__ y,
    const float* __restrict__ bd0, const float* __restrict__ bd1,
    const float* __restrict__ bd2, const float* __restrict__ Wo,
    const float* __restrict__ bo, float* __restrict__ out)
{
#if HAS_TC
    extern __shared__ __align__(1024) unsigned char smem[];
    const u32 sb = smem_u32(smem);
    const int tid = threadIdx.x;
    const int wrp = tid >> 5, lane = tid & 31;
    const int sp = wrp & 3, cho = wrp >> 2;        // cho: 128 gate cols each
    const int row_l = sp * 32 + lane;
    const int row0 = blockIdx.x * 128;
    const int grow = row0 + row_l;
    float* smf = (float*)smem;
    const bool lo_half = (cho < 2);                // owns gate cols [0,256)
    const bool orch = (tid == 480);                // warp 15 lane 0

    if (tid == 0)
        for (int i = 0; i < 6; ++i) MBAR_INIT(sb + OFF_MB + 8 * i, 1);
    if (wrp == 0) T5_ALLOC(sb + OFF_TMEM, 512);
    smf[(OFF_B0P >> 2) + tid] = g_b0p[tid];
    smf[(OFF_WIH >> 2) + tid] = g_wih0p[tid];
    smf[(OFF_B1P >> 2) + tid] = g_b1p[tid];
    if (tid < 256) {
        smf[(OFF_BD >> 2) + tid] = bd0[tid];
        smf[(OFF_BD >> 2) + 256 + tid] = bd1[tid];
        smf[(OFF_BD >> 2) + 512 + tid] = bd2[tid];
    }
    for (int i = tid; i < 1024; i += 512) smf[(OFF_WO >> 2) + i] = Wo[i];
    if (tid < 4) smf[(OFF_BO >> 2) + tid] = bo[tid];
    __syncthreads();
    u32 tmem; asm volatile("ld.shared.b32 %0, [%1];" : "=r"(tmem) : "r"(sb + OFF_TMEM));

    PS ps;
    ps.fullb[0] = sb + OFF_MB;       ps.fullb[1] = sb + OFF_MB + 8;
    ps.emptyb[0] = sb + OFF_MB + 16; ps.emptyb[1] = sb + OFF_MB + 24;
    const u32 gd0 = sb + OFF_MB + 32, gd1 = sb + OFF_MB + 40;
    ps.bbuf[0] = sb + OFF_BBUF; ps.bbuf[1] = sb + OFF_BBUF + 32768;
    ps.fph[0] = ps.fph[1] = ps.eph[0] = ps.eph[1] = 0;
    ps.used[0] = ps.used[1] = 0; ps.sseq = 0; ps.iseq = 0;
    int gph0 = 0, gph1 = 0;

    const float xn = 2.f * x[grow] - 1.f, yn = 2.f * y[grow] - 1.f;
    const u64 dH0hi = mkdesc(sb + A_H0HI);
    const u64 dH1hi = mkdesc(sb + A_H1HI);
    const u64 dAhi  = mkdesc(sb + OFF_AREG);
    const u32 tm_lane = tmem + ((u32)sp << 21);

    for (int t = 0; t < 6; ++t) {
        // ---------- layer 0 GEMM (t>0) ----------
        if (t > 0 && orch) {
            u64 src[8], ad[8]; u32 dstv[8]; int n = 0;
            for (int nh = 0; nh < 2; ++nh)
                for (int kc = 0; kc < 2; ++kc)
                    for (int hl = 0; hl < 2; ++hl) {
                        src[n] = (u64)(uintptr_t)(g_wscr + (size_t)(kc * 4 + nh * 2 + hl) * 32768u);
                        ad[n] = dH0hi + (u64)(kc * 1024);
                        dstv[n] = tmem + (u32)(nh * 256);
                        ++n;
                    }
            run_plan(ps, src, ad, dstv, 8, 4, 3, gd0, gd1);
        }
        // ---------- layer 0 epilogue ----------
        {
            const bool hasg = (t > 0);
            float ft;
            if      (t == 0) ft = xn;
            else if (t == 1) ft = yn;
            else if (t == 2) ft = xn + yn;
            else if (t == 3) ft = xn - yn;
            else if (t == 4) ft = xn * yn;
            else             ft = xn * xn + yn * yn;
            if (hasg) {
                if (lo_half) { MBAR_WAIT(gd0, (u32)gph0); gph0 ^= 1; }
                else         { MBAR_WAIT(gd1, (u32)gph1); gph1 ^= 1; }
                T5_FENCE_A();
            }
            u32 oh[16], ol[16];
            #pragma unroll
            for (int ch = 0; ch < 4; ++ch) {
                const int cb = 128 * cho + 32 * ch;
                const int u0 = 32 * cho + 8 * ch;
                float co[8];
                #pragma unroll
                for (int jj = 0; jj < 8; ++jj)
                    co[jj] = hasg ? g_c0[(size_t)(u0 + jj) * NS + grow] : 0.f;
                u32 r[32];
                if (hasg) { LDTM32(r, tm_lane + (u32)cb); T5_WAIT_LD(); }
                #pragma unroll
                for (int j = 0; j < 8; j += 2) {
                    float h2[2];
                    #pragma unroll
                    for (int q = 0; q < 2; ++q) {
                        const int col = cb + 4 * (j + q);
                        float gi = smf[(OFF_B0P >> 2) + col]     + ft * smf[(OFF_WIH >> 2) + col];
                        float gf = smf[(OFF_B0P >> 2) + col + 1] + ft * smf[(OFF_WIH >> 2) + col + 1];
                        float gg = smf[(OFF_B0P >> 2) + col + 2] + ft * smf[(OFF_WIH >> 2) + col + 2];
                        float go = smf[(OFF_B0P >> 2) + col + 3] + ft * smf[(OFF_WIH >> 2) + col + 3];
                        if (hasg) {
                            gi += __uint_as_float(r[4 * (j + q)]);
                            gf += __uint_as_float(r[4 * (j + q) + 1]);
                            gg += __uint_as_float(r[4 * (j + q) + 2]);
                            go += __uint_as_float(r[4 * (j + q) + 3]);
                        }
                        float cn = siga(gf) * co[j + q] + siga(gi) * tanha(gg);
                        float hn = siga(go) * tanha(cn);
                        g_c0[(size_t)(u0 + j + q) * NS + grow] = cn;
                        h2[q] = hn;
                    }
                    oh[ch * 4 + (j >> 1)] = pack_hl(h2[0], h2[1], ol[ch * 4 + (j >> 1)]);
                }
            }
            if (hasg && lo_half) { MBAR_WAIT(gd1, (u32)gph1); gph1 ^= 1; }
            #pragma unroll
            for (int ch = 0; ch < 4; ++ch)
                #pragma unroll
                for (int jp = 0; jp < 4; ++jp) {
                    int u = 32 * cho + 8 * ch + 2 * jp;
                    u32 base = (u32)((u >> 6) * 16384) + swz((u32)(row_l * 128 + (u & 63) * 2));
                    *(u32*)(smem + A_H0HI + base) = oh[ch * 4 + jp];
                    *(u32*)(smem + A_H0LO + base) = ol[ch * 4 + jp];
                }
            T5_FENCE_B(); FENCE_ASYNC(); __syncthreads();
        }
        // ---------- layer 1 GEMM ----------
        if (orch) {
            u64 src[16], ad[16]; u32 dstv[16]; int n = 0;
            const int nm = (t > 0) ? 2 : 1;
            for (int nh = 0; nh < 2; ++nh)
                for (int m = 0; m < nm; ++m)
                    for (int kc = 0; kc < 2; ++kc)
                        for (int hl = 0; hl < 2; ++hl) {
                            const unsigned char* wb = g_wscr + (size_t)((m == 0) ? 1 : 2) * 262144u;
                            src[n] = (u64)(uintptr_t)(wb + (size_t)(kc * 4 + nh * 2 + hl) * 32768u);
                            ad[n] = ((m == 0) ? dH0hi : dH1hi) + (u64)(kc * 1024);
                            dstv[n] = tmem + (u32)(nh * 256);
                            ++n;
                        }
            run_plan(ps, src, ad, dstv, n, n / 2, n / 2 - 1, gd0, gd1);
        }
        // ---------- layer 1 epilogue ----------
        {
            const bool last = (t == 5);
            if (lo_half) {
                MBAR_WAIT(gd0, (u32)gph0); gph0 ^= 1;
                if (last) { MBAR_WAIT(gd1, (u32)gph1); gph1 ^= 1; }
            } else { MBAR_WAIT(gd1, (u32)gph1); gph1 ^= 1; }
            T5_FENCE_A();
            u32 oh[16], ol[16];
            #pragma unroll
            for (int ch = 0; ch < 4; ++ch) {
                const int cb = 128 * cho + 32 * ch;
                const int u0 = 32 * cho + 8 * ch;
                float co[8], hsv[8];
                #pragma unroll
                for (int jj = 0; jj < 8; ++jj) {
                    co[jj]  = (t > 0) ? g_c1[(size_t)(u0 + jj) * NS + grow] : 0.f;
                    hsv[jj] = (t > 0) ? g_hs[(size_t)(u0 + jj) * NS + grow] : 0.f;
                }
                u32 r[32];
                LDTM32(r, tm_lane + (u32)cb); T5_WAIT_LD();
                #pragma unroll
                for (int j = 0; j < 8; j += 2) {
                    float h2[2], m2[2];
                    #pragma unroll
                    for (int q = 0; q < 2; ++q) {
                        const int col = cb + 4 * (j + q);
                        float gi = __uint_as_float(r[4 * (j + q)])     + smf[(OFF_B1P >> 2) + col];
                        float gf = __uint_as_float(r[4 * (j + q) + 1]) + smf[(OFF_B1P >> 2) + col + 1];
                        float gg = __uint_as_float(r[4 * (j + q) + 2]) + smf[(OFF_B1P >> 2) + col + 2];
                        float go = __uint_as_float(r[4 * (j + q) + 3]) + smf[(OFF_B1P >> 2) + col + 3];
                        float cn = siga(gf) * co[j + q] + siga(gi) * tanha(gg);
                        float hn = siga(go) * tanha(cn);
                        g_c1[(size_t)(u0 + j + q) * NS + grow] = cn;
                        float s = hsv[j + q] + hn;
                        if (!last) g_hs[(size_t)(u0 + j + q) * NS + grow] = s;
                        h2[q] = hn;
                        m2[q] = s * (1.f / 6.f);
                    }
                    const int jp = j >> 1;
                    oh[ch * 4 + jp] = pack_hl(h2[0], h2[1], ol[ch * 4 + jp]);
                    if (last) {
                        int u = u0 + j;
                        u32 base = (u32)((u >> 6) * 16384) + swz((u32)(row_l * 128 + (u & 63) * 2));
                        *(u32*)(smem + A_H1HI + base) = oh[ch * 4 + jp];
                        *(u32*)(smem + A_H1LO + base) = ol[ch * 4 + jp];
                        u32 mlo; u32 mhi = pack_hl(m2[0], m2[1], mlo);
                        *(u32*)(smem + A_H0HI + base) = mhi;   // mean = feat k[128,256)
                        *(u32*)(smem + A_H0LO + base) = mlo;
                    }
                }
            }
            if (!last) {
                if (lo_half) { MBAR_WAIT(gd1, (u32)gph1); gph1 ^= 1; }
                #pragma unroll
                for (int ch = 0; ch < 4; ++ch)
                    #pragma unroll
                    for (int jp = 0; jp < 4; ++jp) {
                        int u = 32 * cho + 8 * ch + 2 * jp;
                        u32 base = (u32)((u >> 6) * 16384) + swz((u32)(row_l * 128 + (u & 63) * 2));
                        *(u32*)(smem + A_H1HI + base) = oh[ch * 4 + jp];
                        *(u32*)(smem + A_H1LO + base) = ol[ch * 4 + jp];
                    }
            }
            T5_FENCE_B(); FENCE_ASYNC(); __syncthreads();
        }
    }

    // ---------- dense stack ----------
    for (int l = 0; l < 3; ++l) {
        if (orch) {
            u64 src[8], ad[8]; u32 dstv[8]; int n = 0;
            const unsigned char* wb = g_wscr + (size_t)(3 + l) * 262144u;
            for (int kc = 0; kc < 4; ++kc)
                for (int hl = 0; hl < 2; ++hl) {
                    src[n] = (u64)(uintptr_t)(wb + (size_t)(kc * 2 + hl) * 32768u);
                    ad[n] = dAhi + (u64)(kc * 1024);
                    dstv[n] = tmem;
                    ++n;
                }
            run_plan(ps, src, ad, dstv, 8, -1, -1, gd0, gd1);
        }
        {
            MBAR_WAIT(gd1, (u32)gph1); gph1 ^= 1;
            T5_FENCE_A();
            const bool fin = (l == 2);
            #pragma unroll
            for (int ch = 0; ch < 2; ++ch) {
                const int cb = 64 * cho + 32 * ch;
                u32 r[32];
                LDTM32(r, tm_lane + (u32)cb); T5_WAIT_LD();
                #pragma unroll
                for (int j = 0; j < 32; j += 2) {
                    int n = cb + j;
                    float a0 = tanha(__uint_as_float(r[j])     + smf[(OFF_BD >> 2) + l * 256 + n]);
                    float a1 = tanha(__uint_as_float(r[j + 1]) + smf[(OFF_BD >> 2) + l * 256 + n + 1]);
                    if (!fin) {
                        u32 base = (u32)((n >> 6) * 16384) + swz((u32)(row_l * 128 + (n & 63) * 2));
                        u32 lo; u32 hi = pack_hl(a0, a1, lo);
                        *(u32*)(smem + OFF_AREG + base) = hi;
                        *(u32*)(smem + OFF_AREG + 65536 + base) = lo;
                    } else {
                        int n2 = n ^ ((row_l & 7) << 2);   // fp32, bank-swizzled
                        *(float2*)(smf + (OFF_AREG >> 2) + row_l * 256 + n2) = make_float2(a0, a1);
                    }
                }
            }
            T5_FENCE_B(); FENCE_ASYNC(); __syncthreads();
        }
    }

    // ---------- output head ----------
    {
        const int rh = tid >> 2, o = tid & 3;
        const float* wo = smf + (OFF_WO >> 2) + o * 256;
        const float* arow = smf + (OFF_AREG >> 2) + rh * 256;
        const int s = (rh & 7) << 2;
        float s0 = 0.f, s1 = 0.f, s2 = 0.f, s3 = 0.f;
        #pragma unroll 8
        for (int kb = 0; kb < 64; ++kb) {
            int k = kb * 4;
            float4 v = *(const float4*)(arow + (k ^ s));
            s0 += v.x * wo[k];
            s1 += v.y * wo[k + 1];
            s2 += v.z * wo[k + 2];
            s3 += v.w * wo[k + 3];
        }
        out[(size_t)(row0 + rh) * 4 + o] = ((s0 + s1) + (s2 + s3)) + smf[(OFF_BO >> 2) + o];
    }

    __syncthreads();
    if (wrp == 0) T5_DEALLOC(tmem, 512);
#endif  // HAS_TC
}

// ============== compact fallback (never taken when tcgen05 exists) =========
__global__ void fb_net(
    const float* __restrict__ x, const float* __restrict__ y,
    const float* __restrict__ Wih0, const float* __restrict__ Whh0, const float* __restrict__ b0,
    const float* __restrict__ Wih1, const float* __restrict__ Whh1, const float* __restrict__ b1,
    const float* __restrict__ Wd0, const float* __restrict__ bd0,
    const float* __restrict__ Wd1, const float* __restrict__ bd1,
    const float* __restrict__ Wd2, const float* __restrict__ bd2,
    const float* __restrict__ Wo,  const float* __restrict__ bo,
    float* __restrict__ out)
{
    if (g_use_tc) return;
    __shared__ float h0[128], c0[128], h1[128], c1[128], hs[128], feat[256], buf[2][256];
    const int u = threadIdx.x;
    for (int s = blockIdx.x; s < NS; s += gridDim.x) {
        float xn = 2.f * x[s] - 1.f, yn = 2.f * y[s] - 1.f;
        h0[u] = c0[u] = h1[u] = c1[u] = hs[u] = 0.f;
        __syncthreads();
        for (int t = 0; t < 6; ++t) {
            float ft = (t == 0) ? xn : (t == 1) ? yn : (t == 2) ? xn + yn
                     : (t == 3) ? xn - yn : (t == 4) ? xn * yn : xn * xn + yn * yn;
            float g[4];
            for (int gi = 0; gi < 4; ++gi) {
                int row = gi * 128 + u;
                float acc = b0[row] + Wih0[row] * ft;
                for (int k = 0; k < 128; ++k) acc += Whh0[row * 128 + k] * h0[k];
                g[gi] = acc;
            }
            float cn = sigf(g[1]) * c0[u] + sigf(g[0]) * tanhf_fast(g[2]);
            float hn = sigf(g[3]) * tanhf_fast(cn);
            __syncthreads();
            c0[u] = cn; h0[u] = hn;
            __syncthreads();
            for (int gi = 0; gi < 4; ++gi) {
                int row = gi * 128 + u;
                float acc = b1[row];
                for (int k = 0; k < 128; ++k)
                    acc += Wih1[row * 128 + k] * h0[k] + Whh1[row * 128 + k] * h1[k];
                g[gi] = acc;
            }
            cn = sigf(g[1]) * c1[u] + sigf(g[0]) * tanhf_fast(g[2]);
            hn = sigf(g[3]) * tanhf_fast(cn);
            __syncthreads();
            c1[u] = cn; h1[u] = hn; hs[u] += hn;
            __syncthreads();
        }
        feat[u] = h1[u]; feat[128 + u] = hs[u] * (1.f / 6.f);
        __syncthreads();
        const float* cur = feat;
        for (int l = 0; l < 3; ++l) {
            const float* W = (l == 0) ? Wd0 : (l == 1) ? Wd1 : Wd2;
            const float* bb = (l == 0) ? bd0 : (l == 1) ? bd1 : bd2;
            float* nxt = buf[l & 1];
            for (int n = u; n < 256; n += 128) {
                float acc = bb[n];
                for (int k = 0; k < 256; ++k) acc += W[n * 256 + k] * cur[k];
                nxt[n] = tanhf_fast(acc);
            }
            __syncthreads();
            cur = nxt;
        }
        if (u < 4) {
            float acc = bo[u];
            for (int k = 0; k < 256; ++k) acc += Wo[u * 256 + k] * cur[k];
            out[(size_t)s * 4 + u] = acc;
        }
        __syncthreads();
    }
}

// ======================= host launcher =====================================
extern "C" void kernel_launch(void* const* d_in, const int* in_sizes, int n_in,
                              void* d_out, int out_size)
{
    const float* x    = (const float*)d_in[0];
    const float* y    = (const float*)d_in[1];
    const float* Wih0 = (const float*)d_in[2];
    const float* Whh0 = (const float*)d_in[3];
    const float* b0   = (const float*)d_in[4];
    const float* Wih1 = (const float*)d_in[5];
    const float* Whh1 = (const float*)d_in[6];
    const float* b1   = (const float*)d_in[7];
    const float* Wd0  = (const float*)d_in[8];
    const float* bd0  = (const float*)d_in[9];
    const float* Wd1  = (const float*)d_in[10];
    const float* bd1  = (const float*)d_in[11];
    const float* Wd2  = (const float*)d_in[12];
    const float* bd2  = (const float*)d_in[13];
    const float* Wo   = (const float*)d_in[14];
    const float* bo   = (const float*)d_in[15];
    float* out = (float*)d_out;

    probe<<<1, 1>>>();
    prep<<<6, 256>>>(Whh0, Wih1, Whh1, Wd0, Wd1, Wd2, Wih0, b0, b1);

    cudaFuncSetAttribute(fused_net, cudaFuncAttributeMaxDynamicSharedMemorySize, SMEM_BYTES);
    fused_net<<<NS / 128, 512, SMEM_BYTES>>>(x, y, bd0, bd1, bd2, Wo, bo, out);

    fb_net<<<512, 128>>>(x, y, Wih0, Whh0, b0, Wih1, Whh1, b1,
                         Wd0, bd0, Wd1, bd1, Wd2, bd2, Wo, bo, out);
}